// round 1
// baseline (speedup 1.0000x reference)
#include <cuda_runtime.h>

#define H      128
#define NREL   237
#define NB     100
#define RTILE  16
#define MT     64
#define SPLIT  4
#define XPITCH 132
#define MAXN   15000
#define MAXE   400000

// ---------------- device-global scratch (no runtime allocation) -------------
__device__ float g_W[NREL * H * H];     // per-relation weights, 15.5 MB
__device__ float g_x0[MAXN * H];        // layer-1 input  (emb gathered via nids)
__device__ float g_h1[MAXN * H];        // layer-1 output / layer-2 input
__device__ int   g_perm[MAXE];          // edge ids sorted by relation
__device__ int   g_counts[256];
__device__ int   g_start[256];
__device__ int   g_cursor[256];

static const int SMEM_BYTES = (H * H + MT * XPITCH) * 4 + MT * 4;  // 99584 B

// ---------------- small prep kernels ----------------------------------------
__global__ void gather_x0_kernel(const float* __restrict__ emb,
                                 const int* __restrict__ nids, int n) {
    int idx = blockIdx.x * blockDim.x + threadIdx.x;   // over n*32 float4
    if (idx < n * 32) {
        int node = idx >> 5, c = idx & 31;
        ((float4*)g_x0)[idx] =
            ((const float4*)emb)[(size_t)nids[node] * 32 + c];
    }
}

__global__ void zero_counts_kernel() {
    g_counts[threadIdx.x] = 0;
}

__global__ void hist_kernel(const int* __restrict__ etype, int E) {
    __shared__ int sh[256];
    sh[threadIdx.x] = 0;
    __syncthreads();
    for (int e = blockIdx.x * blockDim.x + threadIdx.x; e < E;
         e += gridDim.x * blockDim.x)
        atomicAdd(&sh[etype[e]], 1);
    __syncthreads();
    int v = sh[threadIdx.x];
    if (v) atomicAdd(&g_counts[threadIdx.x], v);
}

__global__ void scan_kernel() {
    __shared__ int s[256];
    int t = threadIdx.x;
    int c = g_counts[t];
    s[t] = c;
    __syncthreads();
    #pragma unroll
    for (int off = 1; off < 256; off <<= 1) {
        int v = (t >= off) ? s[t - off] : 0;
        __syncthreads();
        s[t] += v;
        __syncthreads();
    }
    int start = s[t] - c;   // exclusive prefix
    g_start[t]  = start;
    g_cursor[t] = start;
}

__global__ void scatter_kernel(const int* __restrict__ etype, int E) {
    for (int e = blockIdx.x * blockDim.x + threadIdx.x; e < E;
         e += gridDim.x * blockDim.x) {
        int p = atomicAdd(&g_cursor[etype[e]], 1);
        g_perm[p] = e;
    }
}

// W[r] = sum_b comp[r,b] * V[b]   (R=237, B=100, 128x128 each)
__global__ void wbuild_kernel(const float* __restrict__ V,
                              const float* __restrict__ comp) {
    __shared__ float sC[RTILE * NB];
    int r0 = blockIdx.y * RTILE;
    for (int i = threadIdx.x; i < RTILE * NB; i += 128) {
        int rr = i / NB, b = i % NB;
        int r = r0 + rr;
        sC[i] = (r < NREL) ? comp[r * NB + b] : 0.f;
    }
    __syncthreads();
    int j = blockIdx.x * 128 + threadIdx.x;   // 0..16383
    float acc[RTILE];
    #pragma unroll
    for (int rr = 0; rr < RTILE; rr++) acc[rr] = 0.f;
    #pragma unroll 4
    for (int b = 0; b < NB; b++) {
        float v = V[(size_t)b * (H * H) + j];
        #pragma unroll
        for (int rr = 0; rr < RTILE; rr++) acc[rr] += sC[rr * NB + b] * v;
    }
    #pragma unroll
    for (int rr = 0; rr < RTILE; rr++) {
        int r = r0 + rr;
        if (r < NREL) g_W[(size_t)r * (H * H) + j] = acc[rr];
    }
}

__global__ void relu_kernel(int n) {
    for (int i = blockIdx.x * blockDim.x + threadIdx.x; i < n;
         i += gridDim.x * blockDim.x)
        g_h1[i] = fmaxf(g_h1[i], 0.f);
}

// ---------------- dense self-loop GEMM: out = x @ W + bias ------------------
__global__ void node_gemm_kernel(const float* __restrict__ xin,
                                 const float* __restrict__ wmat,
                                 const float* __restrict__ bias,
                                 float* __restrict__ out, int n) {
    extern __shared__ float smem[];
    float* sW = smem;               // 128*128
    float* sX = smem + H * H;       // 64 x 132

    {   // stage W
        const float4* s4 = (const float4*)wmat;
        float4* d4 = (float4*)sW;
        for (int i = threadIdx.x; i < (H * H) / 4; i += 256) d4[i] = s4[i];
    }
    int m0 = blockIdx.x * MT;
    int tsize = min(MT, n - m0);

    int mrow = threadIdx.x >> 2, dg = threadIdx.x & 3;
    if (mrow < tsize) {
        const float4* xr = (const float4*)&xin[(size_t)(m0 + mrow) * H];
        #pragma unroll
        for (int i = 0; i < 8; i++)
            *(float4*)&sX[mrow * XPITCH + dg * 32 + 4 * i] = xr[dg * 8 + i];
    } else {
        float4 z = make_float4(0.f, 0.f, 0.f, 0.f);
        #pragma unroll
        for (int i = 0; i < 8; i++)
            *(float4*)&sX[mrow * XPITCH + dg * 32 + 4 * i] = z;
    }
    __syncthreads();

    int tn = threadIdx.x & 31, tm = threadIdx.x >> 5;
    float acc[8][4];
    #pragma unroll
    for (int r = 0; r < 8; r++)
        #pragma unroll
        for (int c = 0; c < 4; c++) acc[r][c] = 0.f;

    const float* sxb = &sX[tm * 8 * XPITCH];
    #pragma unroll 4
    for (int k = 0; k < H; k++) {
        float4 b = *(const float4*)&sW[k * H + tn * 4];
        #pragma unroll
        for (int r = 0; r < 8; r++) {
            float a = sxb[r * XPITCH + k];
            acc[r][0] += a * b.x; acc[r][1] += a * b.y;
            acc[r][2] += a * b.z; acc[r][3] += a * b.w;
        }
    }
    float4 bj = *(const float4*)&bias[tn * 4];
    #pragma unroll
    for (int r = 0; r < 8; r++) {
        int row = tm * 8 + r;
        if (row < tsize) {
            float4 o = make_float4(acc[r][0] + bj.x, acc[r][1] + bj.y,
                                   acc[r][2] + bj.z, acc[r][3] + bj.w);
            *(float4*)&out[(size_t)(m0 + row) * H + tn * 4] = o;
        }
    }
}

// ---------------- relation-grouped edge GEMM + scatter-add ------------------
__global__ void edge_gemm_kernel(const float* __restrict__ xin,
                                 const int* __restrict__ src,
                                 const int* __restrict__ dst,
                                 const float* __restrict__ norm,
                                 float* __restrict__ hout) {
    extern __shared__ float smem[];
    float* sW = smem;                    // 128*128
    float* sX = smem + H * H;            // 64 x 132
    int*   sD = (int*)(smem + H * H + MT * XPITCH);  // 64

    int rel = blockIdx.x >> 2;
    int s   = blockIdx.x & (SPLIT - 1);
    int cnt = g_counts[rel];
    int st  = g_start[rel];
    int lo  = st + (cnt * s) / SPLIT;
    int hi  = st + (cnt * (s + 1)) / SPLIT;
    if (lo >= hi) return;

    {   // stage W_rel
        const float4* s4 = (const float4*)(g_W + (size_t)rel * H * H);
        float4* d4 = (float4*)sW;
        for (int i = threadIdx.x; i < (H * H) / 4; i += 256) d4[i] = s4[i];
    }

    int tn = threadIdx.x & 31, tm = threadIdx.x >> 5;
    int mrow = threadIdx.x >> 2, dg = threadIdx.x & 3;

    for (int m0 = lo; m0 < hi; m0 += MT) {
        int tsize = min(MT, hi - m0);
        __syncthreads();   // prev-iter readers done (also orders sW on iter 0)
        if (mrow < tsize) {
            int e = g_perm[m0 + mrow];
            float nrm = norm[e];
            if (dg == 0) sD[mrow] = dst[e];
            const float4* xr = (const float4*)&xin[(size_t)src[e] * H];
            #pragma unroll
            for (int i = 0; i < 8; i++) {
                float4 v = xr[dg * 8 + i];
                v.x *= nrm; v.y *= nrm; v.z *= nrm; v.w *= nrm;
                *(float4*)&sX[mrow * XPITCH + dg * 32 + 4 * i] = v;
            }
        } else {
            float4 z = make_float4(0.f, 0.f, 0.f, 0.f);
            #pragma unroll
            for (int i = 0; i < 8; i++)
                *(float4*)&sX[mrow * XPITCH + dg * 32 + 4 * i] = z;
        }
        __syncthreads();

        float acc[8][4];
        #pragma unroll
        for (int r = 0; r < 8; r++)
            #pragma unroll
            for (int c = 0; c < 4; c++) acc[r][c] = 0.f;

        const float* sxb = &sX[tm * 8 * XPITCH];
        #pragma unroll 4
        for (int k = 0; k < H; k++) {
            float4 b = *(const float4*)&sW[k * H + tn * 4];
            #pragma unroll
            for (int r = 0; r < 8; r++) {
                float a = sxb[r * XPITCH + k];
                acc[r][0] += a * b.x; acc[r][1] += a * b.y;
                acc[r][2] += a * b.z; acc[r][3] += a * b.w;
            }
        }
        #pragma unroll
        for (int r = 0; r < 8; r++) {
            int row = tm * 8 + r;
            if (row < tsize) {
                float* p = &hout[(size_t)sD[row] * H + tn * 4];
                atomicAdd(p + 0, acc[r][0]);
                atomicAdd(p + 1, acc[r][1]);
                atomicAdd(p + 2, acc[r][2]);
                atomicAdd(p + 3, acc[r][3]);
            }
        }
    }
}

// ---------------- host orchestration ----------------------------------------
extern "C" void kernel_launch(void* const* d_in, const int* in_sizes, int n_in,
                              void* d_out, int out_size) {
    const int*   nids  = (const int*)d_in[0];
    const int*   src   = (const int*)d_in[1];
    const int*   dst   = (const int*)d_in[2];
    const int*   etype = (const int*)d_in[3];
    const float* norm  = (const float*)d_in[4];
    /* d_in[5] edge_weights unused by the model */
    const float* emb   = (const float*)d_in[6];
    const float* V1    = (const float*)d_in[7];
    const float* comp1 = (const float*)d_in[8];
    const float* loop1 = (const float*)d_in[9];
    const float* bias1 = (const float*)d_in[10];
    const float* V2    = (const float*)d_in[11];
    const float* comp2 = (const float*)d_in[12];
    const float* loop2 = (const float*)d_in[13];
    const float* bias2 = (const float*)d_in[14];
    float* out = (float*)d_out;

    int nN = in_sizes[0];
    int E  = in_sizes[1];

    cudaFuncSetAttribute(node_gemm_kernel,
                         cudaFuncAttributeMaxDynamicSharedMemorySize, SMEM_BYTES);
    cudaFuncSetAttribute(edge_gemm_kernel,
                         cudaFuncAttributeMaxDynamicSharedMemorySize, SMEM_BYTES);

    float *px0 = nullptr, *ph1 = nullptr;
    cudaGetSymbolAddress((void**)&px0, g_x0);
    cudaGetSymbolAddress((void**)&ph1, g_h1);

    // prep: gather input, sort edges by relation
    gather_x0_kernel<<<(nN * 32 + 255) / 256, 256>>>(emb, nids, nN);
    zero_counts_kernel<<<1, 256>>>();
    hist_kernel<<<256, 256>>>(etype, E);
    scan_kernel<<<1, 256>>>();
    scatter_kernel<<<256, 256>>>(etype, E);

    dim3 wgrid(H * H / 128, (NREL + RTILE - 1) / RTILE);
    int ngrid = (nN + MT - 1) / MT;
    int egrid = NREL * SPLIT;

    // ---- layer 1 ----
    wbuild_kernel<<<wgrid, 128>>>(V1, comp1);
    node_gemm_kernel<<<ngrid, 256, SMEM_BYTES>>>(px0, loop1, bias1, ph1, nN);
    edge_gemm_kernel<<<egrid, 256, SMEM_BYTES>>>(px0, src, dst, norm, ph1);
    relu_kernel<<<256, 256>>>(nN * H);

    // ---- layer 2 ----
    wbuild_kernel<<<wgrid, 128>>>(V2, comp2);
    node_gemm_kernel<<<ngrid, 256, SMEM_BYTES>>>(ph1, loop2, bias2, out, nN);
    edge_gemm_kernel<<<egrid, 256, SMEM_BYTES>>>(ph1, src, dst, norm, out);
}

// round 4
// speedup vs baseline: 1.5676x; 1.5676x over previous
#include <cuda_runtime.h>
#include <cstdint>

#define H      128
#define NREL   237
#define NB     100
#define RTILE  16
#define MT     64
#define XPITCH 132
#define MAXN   15000
#define MAXE   400000
#define EM     128        // edges per tile
#define ESPLIT 4          // splits per relation for edge kernel
#define BP     132        // smem pitch (floats) for A and B tiles

// ---------------- device-global scratch (no runtime allocation) -------------
__device__ float g_W[NREL * H * H];     // per-relation W^T[n][k]  (15.5 MB)
__device__ float g_x0[MAXN * H];
__device__ float g_h1[MAXN * H];
__device__ int   g_perm[MAXE];
__device__ int   g_counts[256];
__device__ int   g_start[256];
__device__ int   g_cursor[256];

static const int SMEM_NODE = (H * H + MT * XPITCH) * 4 + MT * 4;     // 99584
static const int SMEM_EDGE = (2 * 128 * BP) * 4 + 128 * 4;           // 135680

// single dynamic-smem symbol for the whole TU
extern __shared__ char dyn_smem[];

// ---------------- PTX helpers ------------------------------------------------
__device__ __forceinline__ uint32_t cvt_tf32(float x) {
    uint32_t r;
    asm("cvt.rn.tf32.f32 %0, %1;" : "=r"(r) : "f"(x));
    return r;
}
__device__ __forceinline__ void red_add_v2(float* p, float a, float b) {
    asm volatile("red.global.add.v2.f32 [%0], {%1,%2};"
                 :: "l"(p), "f"(a), "f"(b) : "memory");
}
__device__ __forceinline__ void mma_16n8k8(float* c, const uint32_t* a,
                                           uint32_t b0, uint32_t b1) {
    asm volatile(
        "mma.sync.aligned.m16n8k8.row.col.f32.tf32.tf32.f32 "
        "{%0,%1,%2,%3}, {%4,%5,%6,%7}, {%8,%9}, {%0,%1,%2,%3};"
        : "+f"(c[0]), "+f"(c[1]), "+f"(c[2]), "+f"(c[3])
        : "r"(a[0]), "r"(a[1]), "r"(a[2]), "r"(a[3]), "r"(b0), "r"(b1));
}
__device__ __forceinline__ uint32_t f2u(float x) { return __float_as_uint(x); }

// ---------------- small prep kernels ----------------------------------------
__global__ void gather_x0_kernel(const float* __restrict__ emb,
                                 const int* __restrict__ nids, int n) {
    int idx = blockIdx.x * blockDim.x + threadIdx.x;
    if (idx < n * 32) {
        int node = idx >> 5, c = idx & 31;
        ((float4*)g_x0)[idx] = ((const float4*)emb)[(size_t)nids[node] * 32 + c];
    }
}
__global__ void zero_counts_kernel() { g_counts[threadIdx.x] = 0; }

__global__ void hist_kernel(const int* __restrict__ etype, int E) {
    __shared__ int sh[256];
    sh[threadIdx.x] = 0;
    __syncthreads();
    for (int e = blockIdx.x * blockDim.x + threadIdx.x; e < E;
         e += gridDim.x * blockDim.x)
        atomicAdd(&sh[etype[e]], 1);
    __syncthreads();
    int v = sh[threadIdx.x];
    if (v) atomicAdd(&g_counts[threadIdx.x], v);
}
__global__ void scan_kernel() {
    __shared__ int s[256];
    int t = threadIdx.x;
    int c = g_counts[t];
    s[t] = c;
    __syncthreads();
    #pragma unroll
    for (int off = 1; off < 256; off <<= 1) {
        int v = (t >= off) ? s[t - off] : 0;
        __syncthreads();
        s[t] += v;
        __syncthreads();
    }
    g_start[t] = s[t] - c;
    g_cursor[t] = s[t] - c;
}
__global__ void scatter_kernel(const int* __restrict__ etype, int E) {
    for (int e = blockIdx.x * blockDim.x + threadIdx.x; e < E;
         e += gridDim.x * blockDim.x) {
        int p = atomicAdd(&g_cursor[etype[e]], 1);
        g_perm[p] = e;
    }
}

// W^T[r][n][k] = sum_b comp[r,b] * V[b][k][n]   (V flat index j = k*128 + n)
__global__ void wbuild_kernel(const float* __restrict__ V,
                              const float* __restrict__ comp) {
    __shared__ float sC[RTILE * NB];
    int r0 = blockIdx.y * RTILE;
    for (int i = threadIdx.x; i < RTILE * NB; i += 128) {
        int rr = i / NB, b = i % NB;
        int r = r0 + rr;
        sC[i] = (r < NREL) ? comp[r * NB + b] : 0.f;
    }
    __syncthreads();
    int j = blockIdx.x * 128 + threadIdx.x;
    float acc[RTILE];
    #pragma unroll
    for (int rr = 0; rr < RTILE; rr++) acc[rr] = 0.f;
    #pragma unroll 4
    for (int b = 0; b < NB; b++) {
        float v = V[(size_t)b * (H * H) + j];
        #pragma unroll
        for (int rr = 0; rr < RTILE; rr++) acc[rr] += sC[rr * NB + b] * v;
    }
    int k = j >> 7, n = j & 127;
    #pragma unroll
    for (int rr = 0; rr < RTILE; rr++) {
        int r = r0 + rr;
        if (r < NREL) g_W[(size_t)r * (H * H) + n * 128 + k] = acc[rr];
    }
}

__global__ void relu_kernel(int n) {
    for (int i = blockIdx.x * blockDim.x + threadIdx.x; i < n;
         i += gridDim.x * blockDim.x)
        g_h1[i] = fmaxf(g_h1[i], 0.f);
}

// ---------------- dense self-loop GEMM: out = x @ W + bias (FFMA) -----------
__global__ void node_gemm_kernel(const float* __restrict__ xin,
                                 const float* __restrict__ wmat,
                                 const float* __restrict__ bias,
                                 float* __restrict__ out, int n) {
    float* smem = (float*)dyn_smem;
    float* sW = smem;
    float* sX = smem + H * H;
    {
        const float4* s4 = (const float4*)wmat;
        float4* d4 = (float4*)sW;
        for (int i = threadIdx.x; i < (H * H) / 4; i += 256) d4[i] = s4[i];
    }
    int m0 = blockIdx.x * MT;
    int tsize = min(MT, n - m0);
    int mrow = threadIdx.x >> 2, dg = threadIdx.x & 3;
    if (mrow < tsize) {
        const float4* xr = (const float4*)&xin[(size_t)(m0 + mrow) * H];
        #pragma unroll
        for (int i = 0; i < 8; i++)
            *(float4*)&sX[mrow * XPITCH + dg * 32 + 4 * i] = xr[dg * 8 + i];
    } else {
        float4 z = make_float4(0.f, 0.f, 0.f, 0.f);
        #pragma unroll
        for (int i = 0; i < 8; i++)
            *(float4*)&sX[mrow * XPITCH + dg * 32 + 4 * i] = z;
    }
    __syncthreads();
    int tn = threadIdx.x & 31, tm = threadIdx.x >> 5;
    float acc[8][4];
    #pragma unroll
    for (int r = 0; r < 8; r++)
        #pragma unroll
        for (int c = 0; c < 4; c++) acc[r][c] = 0.f;
    const float* sxb = &sX[tm * 8 * XPITCH];
    #pragma unroll 4
    for (int k = 0; k < H; k++) {
        float4 b = *(const float4*)&sW[k * H + tn * 4];
        #pragma unroll
        for (int r = 0; r < 8; r++) {
            float a = sxb[r * XPITCH + k];
            acc[r][0] += a * b.x; acc[r][1] += a * b.y;
            acc[r][2] += a * b.z; acc[r][3] += a * b.w;
        }
    }
    float4 bj = *(const float4*)&bias[tn * 4];
    #pragma unroll
    for (int r = 0; r < 8; r++) {
        int row = tm * 8 + r;
        if (row < tsize) {
            float4 o = make_float4(acc[r][0] + bj.x, acc[r][1] + bj.y,
                                   acc[r][2] + bj.z, acc[r][3] + bj.w);
            *(float4*)&out[(size_t)(m0 + row) * H + tn * 4] = o;
        }
    }
}

// ---------------- TF32 mma.sync edge GEMM + vector red scatter --------------
// CTA: 256 threads = 8 warps. Warp (wm, wn): wm in 0..3 (M), wn in 0..1 (N).
// Tile: 128 edges x 128 out, K=128. Warp tile 32x64 via m16n8k8 fragments.
__global__ void __launch_bounds__(256, 1)
edge_mma_kernel(const float* __restrict__ xin,
                const int* __restrict__ src,
                const int* __restrict__ dst,
                const int* __restrict__ perm,
                const float* __restrict__ norm,
                float* __restrict__ hout) {
    float* sA = (float*)dyn_smem;            // [128][BP]  A = norm * x[src] (tf32 bits)
    float* sB = sA + 128 * BP;               // [128][BP]  B = W^T[n][k]    (tf32 bits)
    int*   sDst = (int*)(sB + 128 * BP);     // [128]

    int tid = threadIdx.x, lane = tid & 31, wid = tid >> 5;
    int g = lane >> 2, tig = lane & 3;       // groupID, threadID_in_group
    int wm = wid >> 1, wn = wid & 1;
    int m0 = wm * 32, n0 = wn * 64;

    int rel = blockIdx.x / ESPLIT;
    int sp  = blockIdx.x % ESPLIT;
    int cnt = g_counts[rel], st = g_start[rel];
    int lo = st + (cnt * sp) / ESPLIT;
    int hi = st + (cnt * (sp + 1)) / ESPLIT;
    if (lo >= hi) return;

    // stage B = W^T[rel] once, converted to tf32
    {
        const float4* wt4 = (const float4*)(g_W + (size_t)rel * (H * H));
        for (int i = tid; i < 4096; i += 256) {
            float4 v = wt4[i];
            int n = i >> 5, k = (i & 31) << 2;
            uint4 t = make_uint4(cvt_tf32(v.x), cvt_tf32(v.y),
                                 cvt_tf32(v.z), cvt_tf32(v.w));
            *(uint4*)&sB[n * BP + k] = t;
        }
    }

    int arow = tid >> 1, ahalf = tid & 1;    // staging: 2 threads per edge row

    for (int t0 = lo; t0 < hi; t0 += EM) {
        int tsize = min(EM, hi - t0);
        __syncthreads();   // prior compute done (and B ready on first iter)

        // ---- stage A tile (tf32 bits, normalized) ----
        if (arow < tsize) {
            int e = perm[t0 + arow];
            float nrm = norm[e];
            const float4* xr = (const float4*)(xin + (size_t)src[e] * H);
            if (ahalf == 0) sDst[arow] = dst[e];
            #pragma unroll
            for (int i = 0; i < 16; i++) {
                float4 v = xr[ahalf * 16 + i];
                uint4 t = make_uint4(cvt_tf32(v.x * nrm), cvt_tf32(v.y * nrm),
                                     cvt_tf32(v.z * nrm), cvt_tf32(v.w * nrm));
                *(uint4*)&sA[arow * BP + ahalf * 64 + i * 4] = t;
            }
        } else {
            if (ahalf == 0) sDst[arow] = 0;
            uint4 z = make_uint4(0, 0, 0, 0);
            #pragma unroll
            for (int i = 0; i < 16; i++)
                *(uint4*)&sA[arow * BP + ahalf * 64 + i * 4] = z;
        }
        __syncthreads();

        // ---- compute: warp tile 32x64, K=128 in 16 k-steps of 8 ----
        float acc[2][8][4];
        #pragma unroll
        for (int mi = 0; mi < 2; mi++)
            #pragma unroll
            for (int ni = 0; ni < 8; ni++)
                #pragma unroll
                for (int c = 0; c < 4; c++) acc[mi][ni][c] = 0.f;

        #pragma unroll 2
        for (int ks = 0; ks < 16; ks++) {
            int k0 = ks * 8;
            uint32_t a[2][4];
            #pragma unroll
            for (int mi = 0; mi < 2; mi++) {
                const float* ap = &sA[(m0 + mi * 16 + g) * BP + k0 + tig];
                a[mi][0] = f2u(ap[0]);
                a[mi][1] = f2u(ap[8 * BP]);
                a[mi][2] = f2u(ap[4]);
                a[mi][3] = f2u(ap[8 * BP + 4]);
            }
            #pragma unroll
            for (int ni = 0; ni < 8; ni++) {
                const float* bp = &sB[(n0 + ni * 8 + g) * BP + k0 + tig];
                uint32_t b0 = f2u(bp[0]);
                uint32_t b1 = f2u(bp[4]);
                mma_16n8k8(acc[0][ni], a[0], b0, b1);
                mma_16n8k8(acc[1][ni], a[1], b0, b1);
            }
        }

        // ---- scatter: red.global.add.v2 per (row, n-pair) ----
        #pragma unroll
        for (int mi = 0; mi < 2; mi++) {
            int r_lo = m0 + mi * 16 + g;
            int r_hi = r_lo + 8;
            bool v_lo = r_lo < tsize, v_hi = r_hi < tsize;
            float* plo = hout + (size_t)sDst[r_lo] * H;
            float* phi = hout + (size_t)sDst[r_hi] * H;
            #pragma unroll
            for (int ni = 0; ni < 8; ni++) {
                int c = n0 + ni * 8 + tig * 2;
                if (v_lo) red_add_v2(plo + c, acc[mi][ni][0], acc[mi][ni][1]);
                if (v_hi) red_add_v2(phi + c, acc[mi][ni][2], acc[mi][ni][3]);
            }
        }
    }
}

// ---------------- host orchestration ----------------------------------------
extern "C" void kernel_launch(void* const* d_in, const int* in_sizes, int n_in,
                              void* d_out, int out_size) {
    const int*   nids  = (const int*)d_in[0];
    const int*   src   = (const int*)d_in[1];
    const int*   dst   = (const int*)d_in[2];
    const int*   etype = (const int*)d_in[3];
    const float* norm  = (const float*)d_in[4];
    const float* emb   = (const float*)d_in[6];
    const float* V1    = (const float*)d_in[7];
    const float* comp1 = (const float*)d_in[8];
    const float* loop1 = (const float*)d_in[9];
    const float* bias1 = (const float*)d_in[10];
    const float* V2    = (const float*)d_in[11];
    const float* comp2 = (const float*)d_in[12];
    const float* loop2 = (const float*)d_in[13];
    const float* bias2 = (const float*)d_in[14];
    float* out = (float*)d_out;

    int nN = in_sizes[0];
    int E  = in_sizes[1];

    cudaFuncSetAttribute(node_gemm_kernel,
                         cudaFuncAttributeMaxDynamicSharedMemorySize, SMEM_NODE);
    cudaFuncSetAttribute(edge_mma_kernel,
                         cudaFuncAttributeMaxDynamicSharedMemorySize, SMEM_EDGE);

    float *px0 = nullptr, *ph1 = nullptr;
    int* pperm = nullptr;
    cudaGetSymbolAddress((void**)&px0, g_x0);
    cudaGetSymbolAddress((void**)&ph1, g_h1);
    cudaGetSymbolAddress((void**)&pperm, g_perm);

    gather_x0_kernel<<<(nN * 32 + 255) / 256, 256>>>(emb, nids, nN);
    zero_counts_kernel<<<1, 256>>>();
    hist_kernel<<<256, 256>>>(etype, E);
    scan_kernel<<<1, 256>>>();
    scatter_kernel<<<256, 256>>>(etype, E);

    dim3 wgrid(H * H / 128, (NREL + RTILE - 1) / RTILE);
    int ngrid = (nN + MT - 1) / MT;
    int egrid = NREL * ESPLIT;

    // ---- layer 1 ----
    wbuild_kernel<<<wgrid, 128>>>(V1, comp1);
    node_gemm_kernel<<<ngrid, 256, SMEM_NODE>>>(px0, loop1, bias1, ph1, nN);
    edge_mma_kernel<<<egrid, 256, SMEM_EDGE>>>(px0, src, dst, pperm, norm, ph1);
    relu_kernel<<<256, 256>>>(nN * H);

    // ---- layer 2 ----
    wbuild_kernel<<<wgrid, 128>>>(V2, comp2);
    node_gemm_kernel<<<ngrid, 256, SMEM_NODE>>>(ph1, loop2, bias2, out, nN);
    edge_mma_kernel<<<egrid, 256, SMEM_EDGE>>>(ph1, src, dst, pperm, norm, out);
}